// round 1
// baseline (speedup 1.0000x reference)
#include <cuda_runtime.h>
#include <cuda_bf16.h>

// Problem constants (fixed shapes from reference)
#define LDIM 8192
#define FDIM 100
#define LP1  (LDIM + 1)        // 8193 valid positions
#define NWE  (LDIM / 4)        // 2048 packed expression words
#define EWPAD 2112             // padded word count (need up to index 2073)
#define NTHREADS 1024

__global__ __launch_bounds__(NTHREADS)
void finder_kernel(const int* __restrict__ expr,
                   const int* __restrict__ sub,
                   float* __restrict__ out,
                   int B)
{
    __shared__ unsigned int expr_w[EWPAD];       // packed bytes of expression row + 0xFF sentinel
    __shared__ unsigned int sub_w[32];           // packed bytes of sub row (PAD -> 0x80)
    __shared__ unsigned long long red[32];

    const int b   = blockIdx.x;
    const int tid = threadIdx.x;

    // ---- pack expression row into shared bytes (values are 0..63) ----
    const int4* erow = (const int4*)(expr + (long long)b * LDIM);
    for (int i = tid; i < NWE; i += NTHREADS) {
        int4 v = erow[i];
        expr_w[i] = (unsigned)(v.x & 0xFF)
                  | ((unsigned)(v.y & 0xFF) << 8)
                  | ((unsigned)(v.z & 0xFF) << 16)
                  | ((unsigned)(v.w & 0xFF) << 24);
    }
    // sentinel tail: 0xFF bytes never match any sub byte (<= 0x80)
    for (int i = NWE + tid; i < EWPAD; i += NTHREADS) expr_w[i] = 0xFFFFFFFFu;

    // ---- pack sub row, remapping PAD(0) to 0x80 (matches nothing) ----
    if (tid < FDIM / 4) {
        const int* srow = sub + b * FDIM + tid * 4;
        unsigned w = 0;
        #pragma unroll
        for (int k = 0; k < 4; k++) {
            int v = srow[k];
            unsigned byte = (v == 0) ? 0x80u : (unsigned)(v & 0xFF);
            w |= byte << (8 * k);
        }
        sub_w[tid] = w;
    }
    __syncthreads();

    // ---- sliding match count, vectorized 4 f-positions per __vcmpeq4 ----
    unsigned long long best = 0;
    for (int p = tid; p < LP1; p += NTHREADS) {
        const int q = p >> 2;
        const int r = (p & 3) << 3;
        unsigned e[26];
        #pragma unroll
        for (int j = 0; j < 26; j++) e[j] = expr_w[q + j];

        int cnt = 0;
        #pragma unroll
        for (int j = 0; j < 25; j++) {
            unsigned w = __funnelshift_r(e[j], e[j + 1], r);  // bytes p+4j .. p+4j+3
            cnt += __popc(__vcmpeq4(w, sub_w[j]));            // 8 bits per matching byte
        }
        const unsigned score = (unsigned)(cnt >> 3);
        // key: max score wins; among ties, smaller p wins (first max)
        const unsigned long long key =
            ((unsigned long long)score << 32) | (unsigned)(0x7FFFFFFF - p);
        if (key > best) best = key;
    }

    // ---- warp reduction ----
    #pragma unroll
    for (int off = 16; off; off >>= 1) {
        unsigned long long o = __shfl_xor_sync(0xFFFFFFFFu, best, off);
        if (o > best) best = o;
    }
    const int warp = tid >> 5, lane = tid & 31;
    if (lane == 0) red[warp] = best;
    __syncthreads();

    // ---- cross-warp reduction (32 warps) ----
    if (warp == 0) {
        best = red[lane];
        #pragma unroll
        for (int off = 16; off; off >>= 1) {
            unsigned long long o = __shfl_xor_sync(0xFFFFFFFFu, best, off);
            if (o > best) best = o;
        }
        if (lane == 0) {
            const unsigned score = (unsigned)(best >> 32);
            const unsigned pos   = 0x7FFFFFFFu - (unsigned)(best & 0xFFFFFFFFu);
            out[b]     = (float)pos;    // position[B]
            out[B + b] = (float)score;  // max_score[B,1]
        }
    }
}

extern "C" void kernel_launch(void* const* d_in, const int* in_sizes, int n_in,
                              void* d_out, int out_size)
{
    const int* expr = (const int*)d_in[0];   // [B, 8192] int32
    const int* sub  = (const int*)d_in[1];   // [B, 100]  int32
    float* out = (float*)d_out;              // [2*B] float32: positions then scores

    const int B = in_sizes[1] / FDIM;        // 64
    finder_kernel<<<B, NTHREADS>>>(expr, sub, out, B);
}

// round 2
// speedup vs baseline: 1.1189x; 1.1189x over previous
#include <cuda_runtime.h>
#include <cuda_bf16.h>

#define LDIM   8192
#define FDIM   100
#define BROWS  64
#define SEGS   8
#define SEGLEN 1024          // positions per segment (last seg gets +1 handled via extra group)
#define NTHREADS 256
#define NW     288           // shared packed-expr words per segment (need <= 283)

// Cross-CTA combine scratch (zero-initialized at module load; reset by finalizer each run)
__device__ unsigned long long g_key[BROWS];
__device__ unsigned int       g_cnt[BROWS];

__global__ __launch_bounds__(NTHREADS)
void finder_kernel(const int* __restrict__ expr,
                   const int* __restrict__ sub,
                   float* __restrict__ out,
                   int B)
{
    __shared__ unsigned int expr_s[NW];     // packed bytes of this segment + 0xFF sentinel
    __shared__ unsigned int sub_s[FDIM];    // sub byte splatted x4, PAD(0) -> 0x80808080
    __shared__ unsigned long long red[NTHREADS / 32];

    const int s   = blockIdx.x;             // segment 0..SEGS-1
    const int b   = blockIdx.y;             // batch row
    const int tid = threadIdx.x;
    const int p0  = s * SEGLEN;

    // ---- load + pack this segment of the expression row (values 0..63 -> bytes) ----
    const int* erow = expr + (long long)b * LDIM;
    for (int w = tid; w < NW; w += NTHREADS) {
        const int t = p0 + 4 * w;           // 4-aligned; LDIM % 4 == 0 -> fully in or fully out
        unsigned pk = 0xFFFFFFFFu;          // sentinel: never matches (sub bytes <= 0x80)
        if (t < LDIM) {
            int4 v = *(const int4*)(erow + t);
            pk = (unsigned)(v.x & 0xFF)
               | ((unsigned)(v.y & 0xFF) << 8)
               | ((unsigned)(v.z & 0xFF) << 16)
               | ((unsigned)(v.w & 0xFF) << 24);
        }
        expr_s[w] = pk;
    }

    // ---- splat sub bytes (PAD -> 0x80, matches nothing) ----
    if (tid < FDIM) {
        int v = sub[b * FDIM + tid];
        unsigned byte = (v == 0) ? 0x80u : (unsigned)(v & 0xFF);
        sub_s[tid] = byte * 0x01010101u;
    }
    __syncthreads();

    // ---- each thread: one group of 4 consecutive positions, packed byte counters ----
    // last segment gets one extra group covering p=8192 (extra lanes score 0 via sentinel,
    // and their keys can never win: score 0 with larger position than any valid p)
    const int ngroups = (s == SEGS - 1) ? (SEGLEN / 4 + 1) : (SEGLEN / 4);

    unsigned long long best = 0;
    for (int g = tid; g < ngroups; g += NTHREADS) {
        const int q = g;                    // word index of group base within expr_s
        unsigned e0 = expr_s[q];
        unsigned acc = 0;                   // 4 packed per-position match counters
        #pragma unroll
        for (int fj = 0; fj < FDIM / 4; fj++) {
            const unsigned e1 = expr_s[q + fj + 1];
            unsigned m;
            m = __vcmpeq4(e0,                          sub_s[4 * fj + 0]); acc += m & 0x01010101u;
            m = __vcmpeq4(__funnelshift_r(e0, e1,  8), sub_s[4 * fj + 1]); acc += m & 0x01010101u;
            m = __vcmpeq4(__funnelshift_r(e0, e1, 16), sub_s[4 * fj + 2]); acc += m & 0x01010101u;
            m = __vcmpeq4(__funnelshift_r(e0, e1, 24), sub_s[4 * fj + 3]); acc += m & 0x01010101u;
            e0 = e1;
        }
        const int pg = p0 + 4 * g;
        #pragma unroll
        for (int k = 0; k < 4; k++) {
            const unsigned sc = (acc >> (8 * k)) & 0xFFu;
            // key: higher score wins; on tie, smaller position wins (first max)
            const unsigned long long key =
                ((unsigned long long)sc << 32) | (unsigned)(0x7FFFFFFF - (pg + k));
            if (key > best) best = key;
        }
    }

    // ---- intra-CTA reduction ----
    #pragma unroll
    for (int off = 16; off; off >>= 1) {
        unsigned long long o = __shfl_xor_sync(0xFFFFFFFFu, best, off);
        if (o > best) best = o;
    }
    const int warp = tid >> 5, lane = tid & 31;
    if (lane == 0) red[warp] = best;
    __syncthreads();

    if (tid == 0) {
        #pragma unroll
        for (int w = 1; w < NTHREADS / 32; w++)
            if (red[w] > best) best = red[w];

        // ---- cross-CTA combine: atomicMax + last-CTA finalize ----
        atomicMax(&g_key[b], best);
        __threadfence();
        const unsigned arrived = atomicAdd(&g_cnt[b], 1u);
        if (arrived == SEGS - 1) {          // last segment CTA for this row
            __threadfence();
            const unsigned long long k = atomicMax(&g_key[b], 0ULL);  // atomic read
            const unsigned score = (unsigned)(k >> 32);
            const unsigned pos   = 0x7FFFFFFFu - (unsigned)(k & 0xFFFFFFFFu);
            out[b]     = (float)pos;        // position[B]
            out[B + b] = (float)score;      // max_score[B,1]
            // reset scratch for next (graph-replayed) launch
            g_key[b] = 0ULL;
            g_cnt[b] = 0u;
        }
    }
}

extern "C" void kernel_launch(void* const* d_in, const int* in_sizes, int n_in,
                              void* d_out, int out_size)
{
    const int* expr = (const int*)d_in[0];   // [B, 8192] int32
    const int* sub  = (const int*)d_in[1];   // [B, 100]  int32
    float* out = (float*)d_out;              // [2*B] float32: positions then scores

    const int B = in_sizes[1] / FDIM;        // 64
    dim3 grid(SEGS, B);
    finder_kernel<<<grid, NTHREADS>>>(expr, sub, out, B);
}

// round 3
// speedup vs baseline: 1.8821x; 1.6821x over previous
#include <cuda_runtime.h>

#define LDIM  8192
#define FDIM  100
#define QF    25          // f's per quarter-thread
#define SEG   2048        // positions per CTA
#define BLKS  64          // 32-position blocks per CTA
#define PW    68          // words per bitplane (covers t_local 0..2175)
#define VP    65          // 64 vocab planes + always-zero plane for PAD
#define NTHREADS 256
#define SEGS  4
#define BROWS 64

// cross-CTA combine scratch (zero at load; reset by finalizer each launch)
__device__ unsigned long long g_key[BROWS];
__device__ unsigned int       g_cnt[BROWS];

// carry-save adder: counter bit l += a + b, carry out h (2 LOP3)
__device__ __forceinline__ void CSA(unsigned &h, unsigned &l, unsigned a, unsigned b) {
    unsigned old = l;
    l = old ^ a ^ b;
    h = (old & a) | (old & b) | (a & b);
}

// accumulate 25 f's (FB..FB+24) bitsliced for 32 positions of block `blk`
template<int FB>
__device__ __forceinline__ void accum(const unsigned* __restrict__ pl,
                                      const int* __restrict__ soff,
                                      int blk, unsigned cnt[5])
{
    auto IND = [&](int f) -> unsigned {
        const unsigned* p = pl + soff[f] + blk + (f >> 5);
        return __funnelshift_r(p[0], p[1], f & 31);
    };

    unsigned ones = 0, twos = 0, fours = 0, eights = 0, sixteens = 0;
    unsigned c2[6];
    #pragma unroll
    for (int j = 0; j < 6; j++) {
        unsigned x0 = IND(FB + 4*j + 0);
        unsigned x1 = IND(FB + 4*j + 1);
        unsigned x2 = IND(FB + 4*j + 2);
        unsigned x3 = IND(FB + 4*j + 3);
        unsigned ca, cb;
        CSA(ca, ones, x0, x1);
        CSA(cb, ones, x2, x3);
        CSA(c2[j], twos, ca, cb);
    }
    unsigned c4a, c4b, c4c, c8;
    CSA(c4a, fours, c2[0], c2[1]);
    CSA(c4b, fours, c2[2], c2[3]);
    CSA(c4c, fours, c2[4], c2[5]);
    CSA(c8, eights, c4a, c4b);
    unsigned t = eights & c4c; eights ^= c4c;     // leftover weight-8 carry
    sixteens = c8 | t;                             // both set impossible (sum<=24)

    // 25th f
    unsigned x  = IND(FB + 24);
    unsigned c  = ones  & x;  ones   ^= x;
    unsigned d  = twos  & c;  twos   ^= c;
    unsigned e2 = fours & d;  fours  ^= d;
    unsigned e3 = eights & e2; eights ^= e2;
    sixteens |= e3;                                // >=32 impossible

    cnt[0] = ones; cnt[1] = twos; cnt[2] = fours; cnt[3] = eights; cnt[4] = sixteens;
}

__global__ __launch_bounds__(NTHREADS)
void finder_kernel(const int* __restrict__ expr,
                   const int* __restrict__ sub,
                   float* __restrict__ out, int B)
{
    __shared__ unsigned planes[VP * PW];       // 17.7 KB bitboards
    __shared__ int soff[FDIM];                 // per-f plane word offset
    __shared__ unsigned xbuf[3][BLKS][5];      // f-quarter partials
    __shared__ unsigned long long red[2];

    const int s   = blockIdx.x;                // segment 0..3
    const int b   = blockIdx.y;                // batch row
    const int tid = threadIdx.x;
    const int p0  = s * SEG;

    // ---- zero bitplanes (VP*PW = 4420 words, 16B vectors) ----
    for (int i = tid; i < VP * PW / 4; i += NTHREADS)
        ((uint4*)planes)[i] = make_uint4(0, 0, 0, 0);
    if (tid < FDIM) {
        int v = sub[b * FDIM + tid];
        soff[tid] = (v == 0 ? 64 : v) * PW;    // PAD -> always-zero plane
    }
    __syncthreads();

    // ---- build bitboards: bit t_local of plane expr[t] ----
    const int* erow = expr + b * LDIM;
    for (int i = tid; i < PW * 32 / 4; i += NTHREADS) {   // 544 int4 groups
        const int tl = 4 * i;
        const int tg = p0 + tl;
        if (tg < LDIM) {                       // tg mult of 4 -> tg+3 <= 8191 too
            int4 v = *(const int4*)(erow + tg);
            const int w = tl >> 5;             // same word for all 4 bits
            atomicOr(&planes[v.x * PW + w], 1u << ((tl    ) & 31));
            atomicOr(&planes[v.y * PW + w], 1u << ((tl + 1) & 31));
            atomicOr(&planes[v.z * PW + w], 1u << ((tl + 2) & 31));
            atomicOr(&planes[v.w * PW + w], 1u << ((tl + 3) & 31));
        }
    }
    __syncthreads();

    // ---- bitsliced sliding-match accumulation ----
    const int blk = tid & 63;                  // position block (32 positions)
    const int q   = tid >> 6;                  // f-quarter (warp-uniform)
    unsigned cnt[5];
    switch (q) {
        case 0:  accum<0 >(planes, soff, blk, cnt); break;
        case 1:  accum<25>(planes, soff, blk, cnt); break;
        case 2:  accum<50>(planes, soff, blk, cnt); break;
        default: accum<75>(planes, soff, blk, cnt); break;
    }
    if (q) {
        #pragma unroll
        for (int k = 0; k < 5; k++) xbuf[q - 1][blk][k] = cnt[k];
    }
    __syncthreads();

    if (q == 0) {
        // combine 4 quarters: bitsliced add of three 5-plane numbers
        unsigned r[7] = {cnt[0], cnt[1], cnt[2], cnt[3], cnt[4], 0, 0};
        #pragma unroll
        for (int pq = 0; pq < 3; pq++) {
            unsigned c = 0;
            #pragma unroll
            for (int k = 0; k < 5; k++) {
                unsigned a = r[k], d = xbuf[pq][blk][k];
                r[k] = a ^ d ^ c;
                c = (a & d) | (a & c) | (d & c);
            }
            unsigned t5 = r[5] & c; r[5] ^= c; r[6] |= t5;  // >=128 impossible
        }

        // bitplane max over 32 positions + first index
        unsigned m = 0xFFFFFFFFu, score = 0;
        #pragma unroll
        for (int k = 6; k >= 0; k--) {
            unsigned t  = m & r[k];
            unsigned nz = (t != 0u);
            m = nz ? t : m;
            score += nz << k;
        }
        const int pos = p0 + blk * 32 + (__ffs(m) - 1);
        unsigned long long key = ((unsigned long long)score << 32)
                               | (unsigned)(0x7FFFFFFF - pos);

        #pragma unroll
        for (int off = 16; off; off >>= 1) {
            unsigned long long o = __shfl_xor_sync(0xFFFFFFFFu, key, off);
            if (o > key) key = o;
        }
        if ((tid & 31) == 0) red[tid >> 5] = key;
    }
    __syncthreads();

    if (tid == 0) {
        unsigned long long best = red[0] > red[1] ? red[0] : red[1];
        atomicMax(&g_key[b], best);
        __threadfence();
        const unsigned arrived = atomicAdd(&g_cnt[b], 1u);
        if (arrived == SEGS - 1) {
            __threadfence();
            const unsigned long long k = atomicMax(&g_key[b], 0ULL);  // atomic read
            out[b]     = (float)(0x7FFFFFFFu - (unsigned)(k & 0xFFFFFFFFu));
            out[B + b] = (float)(unsigned)(k >> 32);
            g_key[b] = 0ULL;                  // reset for next graph replay
            g_cnt[b] = 0u;
        }
    }
}

extern "C" void kernel_launch(void* const* d_in, const int* in_sizes, int n_in,
                              void* d_out, int out_size)
{
    const int* expr = (const int*)d_in[0];   // [B, 8192] int32
    const int* sub  = (const int*)d_in[1];   // [B, 100]  int32
    float* out = (float*)d_out;              // [2*B] float32: positions then scores

    const int B = in_sizes[1] / FDIM;        // 64
    dim3 grid(SEGS, B);
    finder_kernel<<<grid, NTHREADS>>>(expr, sub, out, B);
}

// round 4
// speedup vs baseline: 1.9375x; 1.0294x over previous
#include <cuda_runtime.h>

#define LDIM  8192
#define FDIM  100
#define SEG   1024        // positions per CTA
#define SEGS  8
#define BROWS 64
#define PW    40          // words per bitplane (36 used, padded for banks/vec4)
#define PWZ   36          // words actually zeroed/used (covers t_local 0..1151)
#define VP    65          // 64 vocab planes + always-zero plane for PAD
#define NTHREADS 256
#define NGROUPS 288       // int4 token groups loaded per CTA (tokens 0..1151)

// cross-CTA combine scratch (zero at load; reset by finalizer each launch)
__device__ unsigned long long g_key[BROWS];
__device__ unsigned int       g_cnt[BROWS];

__device__ __forceinline__ unsigned IND(const unsigned* __restrict__ pl,
                                        const int* __restrict__ soff,
                                        int f, int blk)
{
    const unsigned* p = pl + soff[f] + blk + (f >> 5);
    return __funnelshift_r(p[0], p[1], f & 31);
}

// accumulate NF f's starting at fb, bitsliced over 32 positions of block blk.
// Two interleaved ripple chains for ILP; NF <= 14 -> 4 counter planes.
template<int NF>
__device__ __forceinline__ void accum(const unsigned* __restrict__ pl,
                                      const int* __restrict__ soff,
                                      int fb, int blk, unsigned cnt[4])
{
    constexpr int H0 = NF / 2, H1 = NF - H0;   // each half <= 7 -> 3 planes
    unsigned o0 = 0, t0 = 0, q0 = 0;
    unsigned o1 = 0, t1 = 0, q1 = 0;
    #pragma unroll
    for (int j = 0; j < H1; j++) {
        if (j < H0) {
            unsigned x = IND(pl, soff, fb + j, blk);
            unsigned c = o0 & x; o0 ^= x;
            unsigned d = t0 & c; t0 ^= c;
            q0 |= d;                           // count <= 7: fours set at most once
        }
        {
            unsigned x = IND(pl, soff, fb + H0 + j, blk);
            unsigned c = o1 & x; o1 ^= x;
            unsigned d = t1 & c; t1 ^= c;
            q1 |= d;
        }
    }
    // merge two 3-plane halves (each <= 7) into 4 planes (<= 14)
    unsigned c0 = o0 & o1;                   cnt[0] = o0 ^ o1;
    unsigned c1 = (t0 & t1) | (t0 & c0) | (t1 & c0);
    cnt[1] = t0 ^ t1 ^ c0;
    unsigned c2 = (q0 & q1) | (q0 & c1) | (q1 & c1);
    cnt[2] = q0 ^ q1 ^ c1;
    cnt[3] = c2;
}

__global__ __launch_bounds__(NTHREADS)
void finder_kernel(const int* __restrict__ expr,
                   const int* __restrict__ sub,
                   float* __restrict__ out, int B)
{
    __shared__ unsigned planes[VP * PW];       // 10.4 KB bitboards
    __shared__ int soff[FDIM];
    __shared__ unsigned xbuf[7][32][4];        // f-group partials (groups 1..7)

    const int s   = blockIdx.x;                // segment 0..7
    const int b   = blockIdx.y;                // batch row
    const int tid = threadIdx.x;
    const int p0  = s * SEG;

    // ---- prefetch gmem into registers (overlaps with shared zeroing) ----
    const int* erow = expr + b * LDIM;
    int4 v0, v1;
    bool h0 = false, h1 = false;
    {
        int tl = 4 * tid, tg = p0 + tl;
        if (tg < LDIM) { v0 = *(const int4*)(erow + tg); h0 = true; }
        tl = 4 * (tid + NTHREADS); tg = p0 + tl;
        if (tid + NTHREADS < NGROUPS && tg < LDIM) {
            v1 = *(const int4*)(erow + tg); h1 = true;
        }
    }
    int sval = 0;
    if (tid < FDIM) sval = sub[b * FDIM + tid];

    // ---- zero bitplanes: 65 planes x 9 uint4 (36 words) ----
    for (int i = tid; i < VP * (PWZ / 4); i += NTHREADS) {
        const int pl = i / (PWZ / 4), wq = i % (PWZ / 4);
        *(uint4*)&planes[pl * PW + wq * 4] = make_uint4(0, 0, 0, 0);
    }
    if (tid < FDIM) soff[tid] = (sval == 0 ? 64 : sval) * PW;  // PAD -> zero plane
    __syncthreads();

    // ---- scatter bitboard bits ----
    if (h0) {
        const int tl = 4 * tid, w = tl >> 5;
        atomicOr(&planes[v0.x * PW + w], 1u << ((tl    ) & 31));
        atomicOr(&planes[v0.y * PW + w], 1u << ((tl + 1) & 31));
        atomicOr(&planes[v0.z * PW + w], 1u << ((tl + 2) & 31));
        atomicOr(&planes[v0.w * PW + w], 1u << ((tl + 3) & 31));
    }
    if (h1) {
        const int tl = 4 * (tid + NTHREADS), w = tl >> 5;
        atomicOr(&planes[v1.x * PW + w], 1u << ((tl    ) & 31));
        atomicOr(&planes[v1.y * PW + w], 1u << ((tl + 1) & 31));
        atomicOr(&planes[v1.z * PW + w], 1u << ((tl + 2) & 31));
        atomicOr(&planes[v1.w * PW + w], 1u << ((tl + 3) & 31));
    }
    __syncthreads();

    // ---- bitsliced accumulation: 8 f-groups x 32 position-blocks ----
    // groups 0..3: 13 f's (fb = 13q); groups 4..7: 12 f's (fb = 52 + 12(q-4))
    const int blk = tid & 31;
    const int q   = tid >> 5;                  // warp-uniform
    unsigned cnt[4];
    if (q < 4) accum<13>(planes, soff, q * 13, blk, cnt);
    else       accum<12>(planes, soff, 52 + (q - 4) * 12, blk, cnt);

    if (q) {
        #pragma unroll
        for (int k = 0; k < 4; k++) xbuf[q - 1][blk][k] = cnt[k];
    }
    __syncthreads();

    if (q == 0) {
        // combine 8 partials: bitsliced add of seven 4-plane numbers
        unsigned r[7] = {cnt[0], cnt[1], cnt[2], cnt[3], 0, 0, 0};
        #pragma unroll
        for (int pq = 0; pq < 7; pq++) {
            unsigned c = 0;
            #pragma unroll
            for (int k = 0; k < 4; k++) {
                unsigned a = r[k], d = xbuf[pq][blk][k];
                r[k] = a ^ d ^ c;
                c = (a & d) | (a & c) | (d & c);
            }
            unsigned t;
            t = r[4] & c; r[4] ^= c; c = t;    // propagate weight-16 carry
            t = r[5] & c; r[5] ^= c; c = t;
            r[6] |= c;                          // score <= 100 < 128
        }

        // bitplane max over 32 positions + first index
        unsigned m = 0xFFFFFFFFu, score = 0;
        #pragma unroll
        for (int k = 6; k >= 0; k--) {
            unsigned t  = m & r[k];
            unsigned nz = (t != 0u);
            m = nz ? t : m;
            score += nz << k;
        }
        const int pos = p0 + blk * 32 + (__ffs(m) - 1);
        unsigned long long key = ((unsigned long long)score << 32)
                               | (unsigned)(0x7FFFFFFF - pos);

        #pragma unroll
        for (int off = 16; off; off >>= 1) {
            unsigned long long o = __shfl_xor_sync(0xFFFFFFFFu, key, off);
            if (o > key) key = o;
        }

        if (tid == 0) {
            atomicMax(&g_key[b], key);
            __threadfence();
            const unsigned arrived = atomicAdd(&g_cnt[b], 1u);
            if (arrived == SEGS - 1) {
                __threadfence();
                const unsigned long long k = atomicMax(&g_key[b], 0ULL); // atomic read
                out[b]     = (float)(0x7FFFFFFFu - (unsigned)(k & 0xFFFFFFFFu));
                out[B + b] = (float)(unsigned)(k >> 32);
                g_key[b] = 0ULL;               // reset for next graph replay
                g_cnt[b] = 0u;
            }
        }
    }
}

extern "C" void kernel_launch(void* const* d_in, const int* in_sizes, int n_in,
                              void* d_out, int out_size)
{
    const int* expr = (const int*)d_in[0];   // [B, 8192] int32
    const int* sub  = (const int*)d_in[1];   // [B, 100]  int32
    float* out = (float*)d_out;              // [2*B] float32: positions then scores

    const int B = in_sizes[1] / FDIM;        // 64
    dim3 grid(SEGS, B);
    finder_kernel<<<grid, NTHREADS>>>(expr, sub, out, B);
}